// round 17
// baseline (speedup 1.0000x reference)
#include <cuda_runtime.h>
#include <math.h>

#define NLEADS 61
#define NB 128
typedef unsigned long long ull;

__device__ float g_preds[NB * NLEADS * 3];
// folded FC: W_eff[l][3][256] = fcw[l] @ w4[l];  b_eff[l][3] = fcw@b4 + fcb
__device__ float g_weff[NLEADS * 3 * 256];
__device__ float g_beff[NLEADS * 3];
// per-batch completion counters (zero-init; reset to 0 by the loss block
// after use so CUDA-graph replays see a clean state)
__device__ int g_cnt[NB];

// ---------------- packed fp32x2 ops (Blackwell) ----------------
__device__ __forceinline__ ull ffma2(ull a, ull b, ull c) {
    ull d;
    asm("fma.rn.f32x2 %0, %1, %2, %3;" : "=l"(d) : "l"(a), "l"(b), "l"(c));
    return d;
}
__device__ __forceinline__ ull pk(float lo, float hi) {
    ull r;
    asm("mov.b64 %0, {%1, %2};" : "=l"(r) : "f"(lo), "f"(hi));
    return r;
}
__device__ __forceinline__ float2 upk(ull v) {
    float2 f;
    asm("mov.b64 {%0, %1}, %2;" : "=f"(f.x), "=f"(f.y) : "l"(v));
    return f;
}
__device__ __forceinline__ float hsum(ull v) {
    const float2 f = upk(v);
    return f.x + f.y;
}

// ---- shared memory layout (floats), 13884 fl = 55.5 KB -> 4 CTAs/SM ----
// A1 stored SPLIT: even columns plane E [8][18][34] then odd plane O.
#define OFF_A1E 0        // 4896 fl
#define OFF_A1O 4896     // 4896 fl (A1 region total 9792)
#define OFF_W1D 9792     // 192 fl (dup pairs)
#define OFF_W2D 9984     // 3072 fl (dup pairs)
#define OFF_B1  13056    // 8
#define OFF_B2  13064    // 16
#define OFF_B3  13080    // 32
#define OFF_WEFF 13112   // 772 fl: W_eff (768) + b_eff (3) + pad
#define SMEM_FLOATS 13884
#define SMEM_BYTES (SMEM_FLOATS*4)   // 55536

// aliases inside the A1 region (valid after L2's read-complete sync)
#define OFF_W3  0        // 6144 fl (RAW w3; natural tap pairs)
#define OFF_A2P 6144     // [16][6][20] = 1920 fl (16B aligned)
#define OFF_A3  8064     // 256 fl (16B aligned)
#define OFF_LG  8320     // 4 (logits x3 + last-block flag)

__global__ void __launch_bounds__(256, 4)
lead_forward_kernel(const float* __restrict__ x,
                    const float* __restrict__ w1g, const float* __restrict__ b1g,
                    const float* __restrict__ w2g, const float* __restrict__ b2g,
                    const float* __restrict__ w3g, const float* __restrict__ b3g,
                    const float* __restrict__ w4g, const float* __restrict__ b4g,
                    const float* __restrict__ fcw, const float* __restrict__ fcb,
                    float* __restrict__ out)
{
    extern __shared__ float sm[];
    float*  sA1E = sm + OFF_A1E;
    float*  sA1O = sm + OFF_A1O;
    float*  sA2p = sm + OFF_A2P;
    float*  sA3  = sm + OFF_A3;
    float*  sLg  = sm + OFF_LG;
    float*  sw1d = sm + OFF_W1D;
    float*  sw2d = sm + OFF_W2D;
    float*  sw3  = sm + OFF_W3;
    float*  sb1  = sm + OFF_B1;
    float*  sb2  = sm + OFF_B2;
    float*  sb3  = sm + OFF_B3;
    float*  swef = sm + OFF_WEFF;

    const int tid = threadIdx.x;
    const int b = blockIdx.x;
    const int l = blockIdx.y;
    const float2 z2 = make_float2(0.f, 0.f);
    const float2* x2 = (const float2*)(x + ((size_t)(b*NLEADS + l))*8000);

    // ---- init: zero ONLY the A1 halo (split layout) ----
    for (int i = tid; i < 8*2*17; i += 256) {
        const int pl = i / 34, sub = i % 34;
        const int row = (sub >= 17) ? 17 : 0;
        const int c2  = sub % 17;
        ((float2*)(sA1E + pl*612 + row*34))[c2] = z2;
        ((float2*)(sA1O + pl*612 + row*34))[c2] = z2;
    }
    if (tid < 128) {
        const int pl = tid >> 4, r = (tid & 15) + 1;
        sA1E[pl*612 + r*34] = 0.0f;
        ((float2*)(sA1E + pl*612 + r*34 + 32))[0] = z2;
        ((float2*)(sA1O + pl*612 + r*34 + 32))[0] = z2;
    }
    // ---- stage dup weight pairs + biases ----
    if (tid < 96) {
        const float v = w1g[l*96 + tid];
        ((float2*)sw1d)[tid] = make_float2(v, v);
    }
    #pragma unroll
    for (int k = 0; k < 6; k++) {
        const int i = tid + k*256;     // 1536 = 6*256 exactly, no guard
        const float v = w2g[l*1536 + i];
        ((float2*)sw2d)[i] = make_float2(v, v);
    }
    if (tid < 8)  sb1[tid] = b1g[l*8 + tid];
    if (tid < 16) sb2[tid] = b2g[l*16 + tid];
    if (tid < 32) sb3[tid] = b3g[l*32 + tid];
    __syncthreads();

    // =====================================================================
    // Layer 1 (pooled-row PAIRS): conv (1->8, 3x4, s(1,2), pad (1,1)(2,2))
    // + pool + relu -> pooled (8,16,63) into split A1 (E/O by col parity).
    // =====================================================================
    for (int pair = tid; pair < 8*63; pair += 256) {
        const int pp = pair / 63, pw = pair - pp*63;
        ull P[6][4];
        #pragma unroll
        for (int r = 0; r < 6; r++) {
            const int sr = 4*pp - 1 + r;                 // x row
            const bool rv = (sr >= 0) & (sr < 32);
            const float2* rp = x2 + sr*125 + (2*pw - 1);
            const float2 pA = (rv && pw > 0)  ? rp[0] : z2;
            const float2 pB =  rv             ? rp[1] : z2;
            const float2 pC = (rv && pw < 62) ? rp[2] : z2;
            P[r][0] = pk(pA.x, pB.x);
            P[r][1] = pk(pA.y, pB.y);
            P[r][2] = pk(pB.x, pC.x);
            P[r][3] = pk(pB.y, pC.y);
        }
        // output stored col j = pw+1 -> E plane if j even else O plane
        const int j = pw + 1;
        float* outb = ((j & 1) ? (sA1O + ((j - 1) >> 1)) : (sA1E + (j >> 1)))
                      + (2*pp + 1)*34;
        #pragma unroll
        for (int co = 0; co < 8; co++) {
            const ulonglong2* wq = (const ulonglong2*)(sw1d + co*24);
            ull a0=0ull, a1=0ull, a2=0ull, a3=0ull;
            #pragma unroll
            for (int jj = 0; jj < 6; jj++) {
                const ulonglong2 q = wq[jj];
                {   const int t = 2*jj, kh = t>>2, kw = t&3;
                    a0 = ffma2(P[kh+0][kw], q.x, a0);
                    a1 = ffma2(P[kh+1][kw], q.x, a1);
                    a2 = ffma2(P[kh+2][kw], q.x, a2);
                    a3 = ffma2(P[kh+3][kw], q.x, a3); }
                {   const int t = 2*jj+1, kh = t>>2, kw = t&3;
                    a0 = ffma2(P[kh+0][kw], q.y, a0);
                    a1 = ffma2(P[kh+1][kw], q.y, a1);
                    a2 = ffma2(P[kh+2][kw], q.y, a2);
                    a3 = ffma2(P[kh+3][kw], q.y, a3); }
            }
            const float bias = sb1[co];
            const float2 f0 = upk(a0), f1 = upk(a1), f2 = upk(a2), f3 = upk(a3);
            const float m0 = fmaxf(fmaxf(f0.x, f0.y), fmaxf(f1.x, f1.y)) + bias;
            const float m1 = fmaxf(fmaxf(f2.x, f2.y), fmaxf(f3.x, f3.y)) + bias;
            outb[co*612]      = fmaxf(m0, 0.0f);
            outb[co*612 + 34] = fmaxf(m1, 0.0f);
        }
    }
    __syncthreads();

    // =====================================================================
    // Layer 2 (R8 mapping, SPLIT reads): conv (8->16, 4x3, s(2,2), pad 1)
    // + pool + relu. (8,16,63) -> pooled (16,4,16).
    // =====================================================================
    {
        const int pos = tid & 63;
        const int cg  = tid >> 6;
        const int ph = pos >> 4, pw = pos & 15;
        ull a0[4], a1[4];
        #pragma unroll
        for (int i = 0; i < 4; i++) { a0[i] = 0ull; a1[i] = 0ull; }

        #pragma unroll 1
        for (int ci = 0; ci < 8; ci++) {
            ull P[6][3];
            #pragma unroll
            for (int r = 0; r < 6; r++) {
                const int off = ci*612 + (4*ph + r)*34 + 2*pw;
                const ull pe = *(const ull*)(sA1E + off);      // (X0, X2)
                const ull po = *(const ull*)(sA1O + off);      // (X1, X3)
                const float x4 = sA1E[off + 2];                // X4
                P[r][0] = pe;
                P[r][1] = po;
                P[r][2] = pk(upk(pe).y, x4);                   // (X2, X4)
            }
            #pragma unroll
            for (int i = 0; i < 4; i++) {
                const int co = cg*4 + i;
                const ulonglong2* wq = (const ulonglong2*)(sw2d + (co*8 + ci)*24);
                #pragma unroll
                for (int jj = 0; jj < 6; jj++) {
                    const ulonglong2 q = wq[jj];
                    const int t0 = 2*jj, t1 = 2*jj + 1;
                    a0[i] = ffma2(P[t0/3][t0%3],     q.x, a0[i]);
                    a1[i] = ffma2(P[t0/3 + 2][t0%3], q.x, a1[i]);
                    a0[i] = ffma2(P[t1/3][t1%3],     q.y, a0[i]);
                    a1[i] = ffma2(P[t1/3 + 2][t1%3], q.y, a1[i]);
                }
            }
        }
        __syncthreads();   // ALL A1 reads done -> safe to overwrite region
        #pragma unroll
        for (int i = 0; i < 4; i++) {
            const int co = cg*4 + i;
            const float2 f0 = upk(a0[i]), f1 = upk(a1[i]);
            const float m = fmaxf(fmaxf(f0.x, f0.y), fmaxf(f1.x, f1.y)) + sb2[co];
            sA2p[co*(6*20) + (ph+1)*20 + (pw+1)] = fmaxf(m, 0.0f);
        }
        // zero A2p halo (rows 0,5 and cols 0,17..19 of each [6][20] plane)
        for (int i = tid; i < 16*20; i += 256) {
            const int ci2 = i / 20, c = i % 20;
            sA2p[ci2*120 + 0*20 + c]  = 0.0f;
            sA2p[ci2*120 + 5*20 + c]  = 0.0f;
        }
        for (int i = tid; i < 16*4; i += 256) {
            const int ci2 = i / 4, r = (i & 3) + 1;
            float* row = sA2p + ci2*120 + r*20;
            row[0] = 0.0f; row[17] = 0.0f; row[18] = 0.0f; row[19] = 0.0f;
        }
    }
    // stage RAW w3 into freed A1 head (coalesced float4)
    {
        const float4* w34 = (const float4*)(w3g + (size_t)l*6144);
        #pragma unroll
        for (int k = 0; k < 6; k++) ((float4*)sw3)[tid + k*256] = w34[tid + k*256];
    }
    __syncthreads();

    // =====================================================================
    // Layer 3 (TAP-PAIRED, 128 threads) + W_eff prefetch (other 128 threads).
    // =====================================================================
    if (tid < 128) {
        const int cp  = tid >> 3;
        const int pos = tid & 7;
        const int ph = pos >> 2, pw = pos & 3;
        ull vA0[2], vA1[2], vB0[2], vB1[2];
        #pragma unroll
        for (int c = 0; c < 2; c++) { vA0[c]=vA1[c]=vB0[c]=vB1[c]=0ull; }

        #pragma unroll 1
        for (int ci = 0; ci < 16; ci++) {
            ull p0[4], p1[4], p2[4];
            #pragma unroll
            for (int r = 0; r < 4; r++) {
                const int base = ci*120 + (2*ph + r)*20 + 4*pw;
                const ulonglong2 q = *(const ulonglong2*)(sA2p + base);
                p0[r] = q.x; p1[r] = q.y;
                p2[r] = *(const ull*)(sA2p + base + 4);
            }
            #pragma unroll
            for (int c = 0; c < 2; c++) {
                const int co = cp*2 + c;
                const ulonglong2* wq = (const ulonglong2*)(sw3 + (co*16 + ci)*12);
                const ulonglong2 q0 = wq[0];
                const ulonglong2 q1 = wq[1];
                const ulonglong2 q2 = wq[2];
                vA0[c] = ffma2(p0[0], q0.x, vA0[c]); vA0[c] = ffma2(p1[0], q0.y, vA0[c]);
                vA0[c] = ffma2(p0[1], q1.x, vA0[c]); vA0[c] = ffma2(p1[1], q1.y, vA0[c]);
                vA0[c] = ffma2(p0[2], q2.x, vA0[c]); vA0[c] = ffma2(p1[2], q2.y, vA0[c]);

                vA1[c] = ffma2(p0[1], q0.x, vA1[c]); vA1[c] = ffma2(p1[1], q0.y, vA1[c]);
                vA1[c] = ffma2(p0[2], q1.x, vA1[c]); vA1[c] = ffma2(p1[2], q1.y, vA1[c]);
                vA1[c] = ffma2(p0[3], q2.x, vA1[c]); vA1[c] = ffma2(p1[3], q2.y, vA1[c]);

                vB0[c] = ffma2(p1[0], q0.x, vB0[c]); vB0[c] = ffma2(p2[0], q0.y, vB0[c]);
                vB0[c] = ffma2(p1[1], q1.x, vB0[c]); vB0[c] = ffma2(p2[1], q1.y, vB0[c]);
                vB0[c] = ffma2(p1[2], q2.x, vB0[c]); vB0[c] = ffma2(p2[2], q2.y, vB0[c]);

                vB1[c] = ffma2(p1[1], q0.x, vB1[c]); vB1[c] = ffma2(p2[1], q0.y, vB1[c]);
                vB1[c] = ffma2(p1[2], q1.x, vB1[c]); vB1[c] = ffma2(p2[2], q1.y, vB1[c]);
                vB1[c] = ffma2(p1[3], q2.x, vB1[c]); vB1[c] = ffma2(p2[3], q2.y, vB1[c]);
            }
        }
        #pragma unroll
        for (int c = 0; c < 2; c++) {
            const int co = cp*2 + c;
            const float a0 = hsum(vA0[c]), a1 = hsum(vA1[c]);
            const float b0 = hsum(vB0[c]), b1 = hsum(vB1[c]);
            const float m = fmaxf(fmaxf(a0, b0), fmaxf(a1, b1)) + sb3[co];
            sA3[co*8 + pos] = fmaxf(m, 0.0f);
        }
    } else {
        // idle half-block prefetches this lead's folded FC weights into smem
        const int i = tid - 128;    // 0..127
        const float4* weff4 = (const float4*)(g_weff + (size_t)l*768);
        float4* swef4 = (float4*)swef;
        #pragma unroll
        for (int k = 0; k < 2; k++) {
            const int idx = i + k*128;
            if (idx < 192) swef4[idx] = weff4[idx];
        }
        if (i < 3) swef[768 + i] = g_beff[l*3 + i];
    }
    __syncthreads();

    // =====================================================================
    // Folded L4+FC (smem-hot): logits[c] = W_eff[l][c] . a3 + b_eff[l][c]
    // =====================================================================
    if (tid < 96) {
        const int c = tid >> 5, lane = tid & 31;
        const ulonglong2* wv = (const ulonglong2*)(swef + c*256) + lane*2;
        const ulonglong2* av = (const ulonglong2*)sA3 + lane*2;
        const ulonglong2 w0 = wv[0], w1 = wv[1];
        const ulonglong2 v0 = av[0], v1 = av[1];
        ull acc = ffma2(w0.x, v0.x, 0ull);
        acc = ffma2(w0.y, v0.y, acc);
        acc = ffma2(w1.x, v1.x, acc);
        acc = ffma2(w1.y, v1.y, acc);
        float s = hsum(acc);
        #pragma unroll
        for (int o = 16; o; o >>= 1) s += __shfl_xor_sync(0xffffffffu, s, o);
        if (lane == 0) sLg[c] = s + swef[768 + c];
    }
    __syncthreads();

    // ---- softmax + completion protocol (one thread) ----
    if (tid == 0) {
        const float m = fmaxf(sLg[0], fmaxf(sLg[1], sLg[2]));
        const float e0 = expf(sLg[0]-m), e1 = expf(sLg[1]-m), e2 = expf(sLg[2]-m);
        const float inv = 1.0f / (e0 + e1 + e2);
        float* outp = g_preds + ((size_t)(b*NLEADS + l))*3;
        outp[0] = e0*inv; outp[1] = e1*inv; outp[2] = e2*inv;
        __threadfence();                       // preds visible before count
        const int old = atomicAdd(&g_cnt[b], 1);
        ((int*)sLg)[3] = (old == NLEADS - 1);  // last block for this batch?
    }
    __syncthreads();

    // =====================================================================
    // Fused loss (only the LAST block per batch): log2-space fusion loss,
    // one warp per class using 96 threads. All 61 blocks' preds for batch b
    // are visible (each fenced before its counter increment).
    // =====================================================================
    if (((int*)sLg)[3]) {
        if (tid < 96) {
            const int c = tid >> 5, lane = tid & 31;
            const float* p = g_preds + (size_t)b*NLEADS*3 + c;
            const int l0 = lane, l1 = lane + 32;
            const bool v0 = l0 < NLEADS, v1 = l1 < NLEADS;
            float p0 = 1.f, p1 = 1.f, g0 = 0.f, g1 = 0.f, s = 0.f;
            if (v0) { p0 = p[l0*3]; g0 = log2f(1.0f - p0); s += g0; }
            if (v1) { p1 = p[l1*3]; g1 = log2f(1.0f - p1); s += g1; }
            #pragma unroll
            for (int o = 16; o; o >>= 1) s += __shfl_xor_sync(0xffffffffu, s, o);

            const float e = 2.0f / (float)(NLEADS - 1);
            float loss = 0.f;
            if (v0) loss += exp2f(e*(s - g0)) * logf(p0);
            if (v1) loss += exp2f(e*(s - g1)) * logf(p1);
            #pragma unroll
            for (int o = 16; o; o >>= 1) loss += __shfl_xor_sync(0xffffffffu, loss, o);
            if (lane == 0) out[b*3 + c] = -loss;
        }
        if (tid == 0) g_cnt[b] = 0;   // reset for next graph replay
    }
}

// =====================================================================
// Fold kernel: grid (61, 3), block 1024. W_eff[l][c][k] = sum_co fcw*w4.
// co-sum split over 4 quarters (q = tid>>8, 16 co each) -> 4x MLP,
// combined via smem reduce.
// =====================================================================
__global__ void __launch_bounds__(1024)
fold_fc_kernel(const float* __restrict__ w4g,
               const float* __restrict__ b4g,
               const float* __restrict__ fcw,
               const float* __restrict__ fcb)
{
    __shared__ float sfc[64];
    __shared__ float sacc[3*256];     // quarters 1..3 partial sums
    const int l = blockIdx.x;
    const int c = blockIdx.y;
    const int tid = threadIdx.x;
    const int k = tid & 255, q = tid >> 8;
    if (tid < 64) sfc[tid] = fcw[l*192 + c*64 + tid];
    __syncthreads();

    const float* w4l = w4g + (size_t)l*64*256 + (size_t)(q*16)*256;
    float acc = 0.f;
    #pragma unroll
    for (int co = 0; co < 16; co++)
        acc += sfc[q*16 + co] * w4l[co*256 + k];   // coalesced across k
    if (q > 0) sacc[(q-1)*256 + k] = acc;
    __syncthreads();
    if (q == 0) {
        // sum in fixed quarter order (deterministic)
        const float total = ((acc + sacc[k]) + sacc[256 + k]) + sacc[512 + k];
        g_weff[((size_t)l*3 + c)*256 + k] = total;
    }
    if (tid == 0) {
        float a = fcb[l*3 + c];
        for (int co = 0; co < 64; co++) a += sfc[co] * b4g[l*64 + co];
        g_beff[l*3 + c] = a;
    }
}

extern "C" void kernel_launch(void* const* d_in, const int* in_sizes, int n_in,
                              void* d_out, int out_size)
{
    const float* x   = (const float*)d_in[0];
    const float* w1  = (const float*)d_in[1];
    const float* b1  = (const float*)d_in[2];
    const float* w2  = (const float*)d_in[3];
    const float* b2  = (const float*)d_in[4];
    const float* w3  = (const float*)d_in[5];
    const float* b3  = (const float*)d_in[6];
    const float* w4  = (const float*)d_in[7];
    const float* b4  = (const float*)d_in[8];
    const float* fcw = (const float*)d_in[9];
    const float* fcb = (const float*)d_in[10];
    float* out = (float*)d_out;

    cudaFuncSetAttribute(lead_forward_kernel,
                         cudaFuncAttributeMaxDynamicSharedMemorySize, SMEM_BYTES);

    dim3 fgrid(NLEADS, 3);
    fold_fc_kernel<<<fgrid, 1024>>>(w4, b4, fcw, fcb);
    dim3 grid(NB, NLEADS);
    lead_forward_kernel<<<grid, 256, SMEM_BYTES>>>(x, w1, b1, w2, b2, w3, b3,
                                                   w4, b4, fcw, fcb, out);
}